// round 3
// baseline (speedup 1.0000x reference)
#include <cuda_runtime.h>

#define NN 100000
#define EE 3200000
#define FIN 512
#define HH 16
#define CC 40
#define SCAN_BLOCKS 98   // ceil(100000/1024)

// ---------------- scratch (device globals; no allocation allowed) ----------
__device__ float g_deg[NN];
__device__ float g_dinv[NN];
__device__ int   g_cnt[NN];
__device__ int   g_tmp[NN];
__device__ int   g_off[NN + 1];
__device__ int   g_cur[NN];
__device__ int   g_bsum[128];
__device__ int   g_boff[128];
__device__ __align__(16) int2  g_csr[EE];          // {row, norm_bits}
__device__ __align__(16) float g_bufA[NN * HH];
__device__ __align__(16) float g_bufHW[NN * HH];

// ---------------- init: deg = 1 (self loop), cnt = 0 ----------------------
__global__ void k_init() {
    int i = blockIdx.x * blockDim.x + threadIdx.x;
    if (i < NN) { g_deg[i] = 1.0f; g_cnt[i] = 0; }
}

// ---------------- per-edge degree + count ---------------------------------
// NOTE: edge_index arrives as int32 (JAX x64 disabled downcasts int64).
__global__ void k_degcnt(const int* __restrict__ ei,
                         const float* __restrict__ ew) {
    int e = blockIdx.x * blockDim.x + threadIdx.x;
    if (e < EE) {
        int c = ei[EE + e];
        atomicAdd(&g_deg[c], ew[e]);
        atomicAdd(&g_cnt[c], 1);
    }
}

__global__ void k_dinv() {
    int i = blockIdx.x * blockDim.x + threadIdx.x;
    if (i < NN) g_dinv[i] = rsqrtf(g_deg[i]);   // deg >= 1 always
}

// ---------------- scan (3 kernels) ----------------------------------------
__global__ void k_scan1() {
    __shared__ int sh[256];
    int t = threadIdx.x;
    int base = blockIdx.x * 1024 + t * 4;
    int v[4]; int s = 0;
#pragma unroll
    for (int i = 0; i < 4; i++) {
        v[i] = (base + i < NN) ? g_cnt[base + i] : 0;
        s += v[i];
    }
    sh[t] = s; __syncthreads();
    for (int d = 1; d < 256; d <<= 1) {
        int x = (t >= d) ? sh[t - d] : 0;
        __syncthreads();
        sh[t] += x;
        __syncthreads();
    }
    int run = sh[t] - s;  // exclusive prefix of this thread's chunk
#pragma unroll
    for (int i = 0; i < 4; i++) {
        run += v[i];
        if (base + i < NN) g_tmp[base + i] = run;   // inclusive within block
    }
    if (t == 255) g_bsum[blockIdx.x] = sh[255];
}

__global__ void k_scan2() {
    __shared__ int sh[128];
    int t = threadIdx.x;
    int v = (t < SCAN_BLOCKS) ? g_bsum[t] : 0;
    sh[t] = v; __syncthreads();
    for (int d = 1; d < 128; d <<= 1) {
        int x = (t >= d) ? sh[t - d] : 0;
        __syncthreads();
        sh[t] += x;
        __syncthreads();
    }
    g_boff[t] = sh[t] - v;
    if (t == 127) g_off[NN] = sh[127];   // == EE
}

__global__ void k_scan3() {
    int t = threadIdx.x;
    int base = blockIdx.x * 1024 + t * 4;
    int bo = g_boff[blockIdx.x];
#pragma unroll
    for (int i = 0; i < 4; i++) {
        int idx = base + i;
        if (idx < NN) {
            int o = bo + g_tmp[idx] - g_cnt[idx];  // exclusive offset
            g_off[idx] = o;
            g_cur[idx] = o;
        }
    }
}

// ---------------- scatter edges into CSR with precomputed norm ------------
__global__ void k_scatter(const int* __restrict__ ei,
                          const float* __restrict__ ew) {
    int e = blockIdx.x * blockDim.x + threadIdx.x;
    if (e < EE) {
        int r = ei[e];
        int c = ei[EE + e];
        float nm = g_dinv[r] * ew[e] * g_dinv[c];
        int pos = atomicAdd(&g_cur[c], 1);
        g_csr[pos] = make_int2(r, __float_as_int(nm));
    }
}

// ---------------- gemm1: bufA = relu(x @ W_first + b) ---------------------
// block = 128 threads handles 256 rows (2 rows/thread), feature tiles of 32.
__global__ __launch_bounds__(128) void k_gemm1(const float* __restrict__ x,
                                               const float* __restrict__ W,
                                               const float* __restrict__ b) {
    __shared__ float xs[256 * 33];
    int t = threadIdx.x;
    int rowbase = blockIdx.x * 256;
    float acc0[16], acc1[16];
#pragma unroll
    for (int k = 0; k < 16; k++) { acc0[k] = 0.f; acc1[k] = 0.f; }

    const float4* x4 = (const float4*)x;
    const float4* W4 = (const float4*)W;

    for (int tile = 0; tile < 16; tile++) {
        __syncthreads();
        // stage 256 rows x 32 features, coalesced global, conflict-free smem
#pragma unroll
        for (int i = 0; i < 16; i++) {
            int idx = i * 128 + t;
            int r = idx >> 3, f4 = idx & 7;
            int grow = rowbase + r;
            float4 v = make_float4(0.f, 0.f, 0.f, 0.f);
            if (grow < NN) v = x4[grow * (FIN / 4) + tile * 8 + f4];
            float* dst = &xs[r * 33 + f4 * 4];
            dst[0] = v.x; dst[1] = v.y; dst[2] = v.z; dst[3] = v.w;
        }
        __syncthreads();
#pragma unroll 8
        for (int f = 0; f < 32; f++) {
            float xv0 = xs[t * 33 + f];
            float xv1 = xs[(t + 128) * 33 + f];
            int fg = tile * 32 + f;
#pragma unroll
            for (int k4 = 0; k4 < 4; k4++) {
                float4 w = __ldg(&W4[fg * 4 + k4]);
                acc0[k4 * 4 + 0] += xv0 * w.x; acc1[k4 * 4 + 0] += xv1 * w.x;
                acc0[k4 * 4 + 1] += xv0 * w.y; acc1[k4 * 4 + 1] += xv1 * w.y;
                acc0[k4 * 4 + 2] += xv0 * w.z; acc1[k4 * 4 + 2] += xv1 * w.z;
                acc0[k4 * 4 + 3] += xv0 * w.w; acc1[k4 * 4 + 3] += xv1 * w.w;
            }
        }
    }
    const float4* b4 = (const float4*)b;
    float4* out4 = (float4*)g_bufA;
    int r0 = rowbase + t;
    int r1 = rowbase + t + 128;
#pragma unroll
    for (int k4 = 0; k4 < 4; k4++) {
        float4 bb = __ldg(&b4[k4]);
        if (r0 < NN) {
            float4 o;
            o.x = fmaxf(acc0[k4 * 4 + 0] + bb.x, 0.f);
            o.y = fmaxf(acc0[k4 * 4 + 1] + bb.y, 0.f);
            o.z = fmaxf(acc0[k4 * 4 + 2] + bb.z, 0.f);
            o.w = fmaxf(acc0[k4 * 4 + 3] + bb.w, 0.f);
            out4[r0 * 4 + k4] = o;
        }
        if (r1 < NN) {
            float4 o;
            o.x = fmaxf(acc1[k4 * 4 + 0] + bb.x, 0.f);
            o.y = fmaxf(acc1[k4 * 4 + 1] + bb.y, 0.f);
            o.z = fmaxf(acc1[k4 * 4 + 2] + bb.z, 0.f);
            o.w = fmaxf(acc1[k4 * 4 + 3] + bb.w, 0.f);
            out4[r1 * 4 + k4] = o;
        }
    }
}

// ---------------- mm16: bufHW = bufA @ W (16x16) --------------------------
__global__ __launch_bounds__(256) void k_mm16(const float* __restrict__ W) {
    __shared__ float Ws[256];
    Ws[threadIdx.x] = W[threadIdx.x];
    __syncthreads();
    int idx = blockIdx.x * blockDim.x + threadIdx.x;
    if (idx >= NN) return;
    const float4* in4 = (const float4*)g_bufA;
    float xr[16];
#pragma unroll
    for (int q = 0; q < 4; q++) {
        float4 v = in4[idx * 4 + q];
        xr[q * 4 + 0] = v.x; xr[q * 4 + 1] = v.y;
        xr[q * 4 + 2] = v.z; xr[q * 4 + 3] = v.w;
    }
    float acc[16];
#pragma unroll
    for (int k = 0; k < 16; k++) acc[k] = 0.f;
#pragma unroll
    for (int f = 0; f < 16; f++) {
        float xv = xr[f];
#pragma unroll
        for (int k = 0; k < 16; k++) acc[k] += xv * Ws[f * 16 + k];
    }
    float4* out4 = (float4*)g_bufHW;
#pragma unroll
    for (int q = 0; q < 4; q++) {
        float4 o;
        o.x = acc[q * 4 + 0]; o.y = acc[q * 4 + 1];
        o.z = acc[q * 4 + 2]; o.w = acc[q * 4 + 3];
        out4[idx * 4 + q] = o;
    }
}

// ---------------- aggregation: bufA = relu(gather(bufHW) + b) -------------
// half-warp (16 lanes) per node; gather-based, no atomics.
__global__ __launch_bounds__(256) void k_agg(const float* __restrict__ bias) {
    int tid = blockIdx.x * 256 + threadIdx.x;     // grid sized to NN*16 exactly
    int node = tid >> 4;
    int k = tid & 15;
    int lane = threadIdx.x & 31;
    unsigned mask = (lane < 16) ? 0x0000FFFFu : 0xFFFF0000u;

    int o0 = g_off[node];
    int o1 = g_off[node + 1];
    float dv = g_dinv[node];
    const float* hw = g_bufHW;
    float acc = dv * dv * hw[node * 16 + k];      // self loop (weight 1)

    for (int e = o0; e < o1; e += 16) {
        int idx = e + k;
        int2 pr = make_int2(0, 0);
        if (idx < o1) pr = g_csr[idx];
#pragma unroll
        for (int j = 0; j < 16; j++) {
            int   rr = __shfl_sync(mask, pr.x, j, 16);
            float nm = __int_as_float(__shfl_sync(mask, pr.y, j, 16));
            acc += nm * hw[rr * 16 + k];          // nm==0 padding is harmless
        }
    }
    g_bufA[node * 16 + k] = fmaxf(acc + bias[k], 0.0f);
}

// ---------------- output: logits (16x40) + log_softmax --------------------
__global__ __launch_bounds__(256) void k_out(const float* __restrict__ Wo,
                                             const float* __restrict__ bo,
                                             float* __restrict__ out) {
    __shared__ float Ws[16 * 40];
    __shared__ float bs[40];
    for (int i = threadIdx.x; i < 640; i += 256) Ws[i] = Wo[i];
    if (threadIdx.x < 40) bs[threadIdx.x] = bo[threadIdx.x];
    __syncthreads();
    int idx = blockIdx.x * blockDim.x + threadIdx.x;
    if (idx >= NN) return;

    const float4* in4 = (const float4*)g_bufA;
    float hx[16];
#pragma unroll
    for (int q = 0; q < 4; q++) {
        float4 v = in4[idx * 4 + q];
        hx[q * 4 + 0] = v.x; hx[q * 4 + 1] = v.y;
        hx[q * 4 + 2] = v.z; hx[q * 4 + 3] = v.w;
    }
    float acc[40];
#pragma unroll
    for (int c = 0; c < 40; c++) acc[c] = bs[c];
#pragma unroll
    for (int f = 0; f < 16; f++) {
        float xv = hx[f];
#pragma unroll
        for (int c = 0; c < 40; c++) acc[c] += xv * Ws[f * 40 + c];
    }
    float m = acc[0];
#pragma unroll
    for (int c = 1; c < 40; c++) m = fmaxf(m, acc[c]);
    float s = 0.f;
#pragma unroll
    for (int c = 0; c < 40; c++) s += __expf(acc[c] - m);
    float lse = m + __logf(s);
#pragma unroll
    for (int c = 0; c < 40; c++) out[idx * 40 + c] = acc[c] - lse;
}

// ---------------- launch ---------------------------------------------------
extern "C" void kernel_launch(void* const* d_in, const int* in_sizes, int n_in,
                              void* d_out, int out_size) {
    const float* x  = (const float*)d_in[0];
    const int*   ei = (const int*)d_in[1];     // int32! (JAX x64 disabled)
    const float* ew = (const float*)d_in[2];
    const float* Wf = (const float*)d_in[3];
    const float* bf = (const float*)d_in[4];
    const float* W1 = (const float*)d_in[5];
    const float* b1 = (const float*)d_in[6];
    const float* W2 = (const float*)d_in[7];
    const float* b2 = (const float*)d_in[8];
    const float* Wo = (const float*)d_in[9];
    const float* bo = (const float*)d_in[10];
    float* out = (float*)d_out;

    int nb_n = (NN + 255) / 256;          // 391
    int nb_e = (EE + 255) / 256;          // 12500

    k_init  <<<nb_n, 256>>>();
    k_degcnt<<<nb_e, 256>>>(ei, ew);
    k_dinv  <<<nb_n, 256>>>();
    k_scan1 <<<SCAN_BLOCKS, 256>>>();
    k_scan2 <<<1, 128>>>();
    k_scan3 <<<SCAN_BLOCKS, 256>>>();
    k_scatter<<<nb_e, 256>>>(ei, ew);

    k_gemm1 <<<(NN + 255) / 256, 128>>>(x, Wf, bf);

    k_mm16  <<<nb_n, 256>>>(W1);
    k_agg   <<<(NN * 16) / 256, 256>>>(b1);

    k_mm16  <<<nb_n, 256>>>(W2);
    k_agg   <<<(NN * 16) / 256, 256>>>(b2);

    k_out   <<<nb_n, 256>>>(Wo, bo, out);
}

// round 4
// speedup vs baseline: 1.0780x; 1.0780x over previous
#include <cuda_runtime.h>

#define NN 100000
#define EE 3200000
#define FIN 512
#define HH 16
#define CC 40
#define SCAN_BLOCKS 98   // ceil(100000/1024)

typedef unsigned long long u64;

// ---------------- scratch (device globals; no allocation allowed) ----------
__device__ u64   g_pack[NN];         // (cnt<<40) | fixed24(sum ew)
__device__ float g_dinv[NN];
__device__ int   g_cnt[NN];
__device__ int   g_tmp[NN];
__device__ int   g_off[NN + 1];
__device__ int   g_cur[NN];
__device__ int   g_bsum[128];
__device__ int   g_boff[128];
__device__ __align__(16) int2  g_csr[EE];          // {row, norm_bits}
__device__ __align__(16) float g_bufA[NN * HH];
__device__ __align__(16) float g_bufB[NN * HH];

// ---------------- packed f32x2 helpers -------------------------------------
__device__ __forceinline__ void ffma2(u64& d, u64 a, u64 b) {
    asm("fma.rn.f32x2 %0, %1, %2, %0;" : "+l"(d) : "l"(a), "l"(b));
}
__device__ __forceinline__ u64 pack2(float a, float b) {
    u64 r; asm("mov.b64 %0, {%1, %2};" : "=l"(r) : "f"(a), "f"(b)); return r;
}
__device__ __forceinline__ float2 unpack2(u64 v) {
    float2 r; asm("mov.b64 {%0, %1}, %2;" : "=f"(r.x), "=f"(r.y) : "l"(v)); return r;
}

// ---------------- init ------------------------------------------------------
__global__ void k_init() {
    int i = blockIdx.x * blockDim.x + threadIdx.x;
    if (i < NN) g_pack[i] = 0ull;
}

// ---------------- per-edge degree+count: ONE 64-bit atomic per edge --------
// edge_index is int32 (JAX x64 disabled).
__global__ void k_degcnt(const int* __restrict__ ei,
                         const float* __restrict__ ew) {
    int e = blockIdx.x * blockDim.x + threadIdx.x;
    if (e < EE) {
        int c = ei[EE + e];
        u64 p = (1ull << 40) | (u64)__float2uint_rn(ew[e] * 16777216.0f);
        atomicAdd(&g_pack[c], p);
    }
}

// ---------------- scan pass 1 (+ extract cnt, compute dinv) ----------------
__global__ void k_scan1() {
    __shared__ int sh[256];
    int t = threadIdx.x;
    int base = blockIdx.x * 1024 + t * 4;
    int v[4]; int s = 0;
#pragma unroll
    for (int i = 0; i < 4; i++) {
        int idx = base + i;
        int c = 0;
        if (idx < NN) {
            u64 p = g_pack[idx];
            c = (int)(p >> 40);
            g_cnt[idx] = c;
            float deg = 1.0f + (float)(p & 0xFFFFFFFFFFull) * 5.9604645e-8f;
            g_dinv[idx] = rsqrtf(deg);
        }
        v[i] = c; s += c;
    }
    sh[t] = s; __syncthreads();
    for (int d = 1; d < 256; d <<= 1) {
        int x = (t >= d) ? sh[t - d] : 0;
        __syncthreads();
        sh[t] += x;
        __syncthreads();
    }
    int run = sh[t] - s;
#pragma unroll
    for (int i = 0; i < 4; i++) {
        run += v[i];
        if (base + i < NN) g_tmp[base + i] = run;   // inclusive within block
    }
    if (t == 255) g_bsum[blockIdx.x] = sh[255];
}

__global__ void k_scan2() {
    __shared__ int sh[128];
    int t = threadIdx.x;
    int v = (t < SCAN_BLOCKS) ? g_bsum[t] : 0;
    sh[t] = v; __syncthreads();
    for (int d = 1; d < 128; d <<= 1) {
        int x = (t >= d) ? sh[t - d] : 0;
        __syncthreads();
        sh[t] += x;
        __syncthreads();
    }
    g_boff[t] = sh[t] - v;
    if (t == 127) g_off[NN] = sh[127];   // == EE
}

__global__ void k_scan3() {
    int t = threadIdx.x;
    int base = blockIdx.x * 1024 + t * 4;
    int bo = g_boff[blockIdx.x];
#pragma unroll
    for (int i = 0; i < 4; i++) {
        int idx = base + i;
        if (idx < NN) {
            int o = bo + g_tmp[idx] - g_cnt[idx];  // exclusive offset
            g_off[idx] = o;
            g_cur[idx] = o;
        }
    }
}

// ---------------- scatter edges into CSR with precomputed norm ------------
__global__ void k_scatter(const int* __restrict__ ei,
                          const float* __restrict__ ew) {
    int e = blockIdx.x * blockDim.x + threadIdx.x;
    if (e < EE) {
        int r = ei[e];
        int c = ei[EE + e];
        float nm = g_dinv[r] * ew[e] * g_dinv[c];
        int pos = atomicAdd(&g_cur[c], 1);
        g_csr[pos] = make_int2(r, __float_as_int(nm));
    }
}

// ---------------- gemm1: bufA = relu(x @ W_first + b), packed f32x2 -------
// block = 128 threads handles 256 rows (2 rows/thread), feature tiles of 32.
__global__ __launch_bounds__(128) void k_gemm1(const float* __restrict__ x,
                                               const float* __restrict__ W,
                                               const float* __restrict__ b) {
    __shared__ float xs[256 * 33];
    int t = threadIdx.x;
    int rowbase = blockIdx.x * 256;
    u64 acc0[8], acc1[8];
#pragma unroll
    for (int k = 0; k < 8; k++) { acc0[k] = 0ull; acc1[k] = 0ull; }

    const float4*     x4 = (const float4*)x;
    const ulonglong2* Wp = (const ulonglong2*)W;   // W row = 64B = 4 x ulonglong2

    for (int tile = 0; tile < 16; tile++) {
        __syncthreads();
        // stage 256 rows x 32 features: coalesced global, conflict-free smem
#pragma unroll
        for (int i = 0; i < 16; i++) {
            int idx = i * 128 + t;
            int r = idx >> 3, f4 = idx & 7;
            int grow = rowbase + r;
            float4 v = make_float4(0.f, 0.f, 0.f, 0.f);
            if (grow < NN) v = x4[grow * (FIN / 4) + tile * 8 + f4];
            float* dst = &xs[r * 33 + f4 * 4];
            dst[0] = v.x; dst[1] = v.y; dst[2] = v.z; dst[3] = v.w;
        }
        __syncthreads();
#pragma unroll 8
        for (int f = 0; f < 32; f++) {
            float xv0 = xs[t * 33 + f];
            float xv1 = xs[(t + 128) * 33 + f];
            u64 xp0 = pack2(xv0, xv0);
            u64 xp1 = pack2(xv1, xv1);
            int fg = tile * 32 + f;
#pragma unroll
            for (int q = 0; q < 4; q++) {
                ulonglong2 wp = __ldg(&Wp[fg * 4 + q]);
                ffma2(acc0[q * 2 + 0], xp0, wp.x);
                ffma2(acc0[q * 2 + 1], xp0, wp.y);
                ffma2(acc1[q * 2 + 0], xp1, wp.x);
                ffma2(acc1[q * 2 + 1], xp1, wp.y);
            }
        }
    }
    const float4* b4 = (const float4*)b;
    float4* out4 = (float4*)g_bufA;
    int r0 = rowbase + t;
    int r1 = rowbase + t + 128;
#pragma unroll
    for (int k4 = 0; k4 < 4; k4++) {
        float4 bb = __ldg(&b4[k4]);
        float2 a0 = unpack2(acc0[k4 * 2 + 0]);
        float2 a1 = unpack2(acc0[k4 * 2 + 1]);
        float2 c0 = unpack2(acc1[k4 * 2 + 0]);
        float2 c1 = unpack2(acc1[k4 * 2 + 1]);
        if (r0 < NN) {
            float4 o;
            o.x = fmaxf(a0.x + bb.x, 0.f);
            o.y = fmaxf(a0.y + bb.y, 0.f);
            o.z = fmaxf(a1.x + bb.z, 0.f);
            o.w = fmaxf(a1.y + bb.w, 0.f);
            out4[r0 * 4 + k4] = o;
        }
        if (r1 < NN) {
            float4 o;
            o.x = fmaxf(c0.x + bb.x, 0.f);
            o.y = fmaxf(c0.y + bb.y, 0.f);
            o.z = fmaxf(c1.x + bb.z, 0.f);
            o.w = fmaxf(c1.y + bb.w, 0.f);
            out4[r1 * 4 + k4] = o;
        }
    }
}

// ---------------- fused conv layer: hout = relu((A @ hin) @ W + b) --------
// half-warp (16 lanes) per node; gather-based, no atomics, no shuffles.
// Uses (A@h)@W == A@(hW): aggregate first, then 16x16 transform via smem.
__global__ __launch_bounds__(256) void k_agg(const float* __restrict__ hin,
                                             float* __restrict__ hout,
                                             const float* __restrict__ W,
                                             const float* __restrict__ bias) {
    __shared__ float Ws[256];
    __shared__ float bs[16];
    __shared__ float hb[256];
    Ws[threadIdx.x] = W[threadIdx.x];
    if (threadIdx.x < 16) bs[threadIdx.x] = bias[threadIdx.x];
    __syncthreads();

    int tid = blockIdx.x * 256 + threadIdx.x;     // grid = NN*16/256 exactly
    int node = tid >> 4;
    int k = tid & 15;

    int o0 = g_off[node];
    int o1 = g_off[node + 1];
    float dv = g_dinv[node];
    float acc = dv * dv * hin[node * 16 + k];     // self loop (weight 1)

    for (int e = o0; e < o1; e += 16) {
#pragma unroll
        for (int j = 0; j < 16; j++) {
            int idx = e + j;
            if (idx < o1) {
                int2 pr = __ldg(&g_csr[idx]);     // uniform across half-warp
                acc += __int_as_float(pr.y) * hin[pr.x * 16 + k];
            }
        }
    }

    // 16x16 transform: exchange the 16 aggregated feats within the half-warp
    hb[threadIdx.x] = acc;
    __syncwarp();
    int base = threadIdx.x & ~15;
    float o = bs[k];
#pragma unroll
    for (int f = 0; f < 16; f++) o += hb[base + f] * Ws[f * 16 + k];
    hout[node * 16 + k] = fmaxf(o, 0.0f);
}

// ---------------- output: logits (16x40) + log_softmax --------------------
__global__ __launch_bounds__(256) void k_out(const float* __restrict__ Wo,
                                             const float* __restrict__ bo,
                                             float* __restrict__ out) {
    __shared__ float Ws[16 * 40];
    __shared__ float bs[40];
    for (int i = threadIdx.x; i < 640; i += 256) Ws[i] = Wo[i];
    if (threadIdx.x < 40) bs[threadIdx.x] = bo[threadIdx.x];
    __syncthreads();
    int idx = blockIdx.x * blockDim.x + threadIdx.x;
    if (idx >= NN) return;

    const float4* in4 = (const float4*)g_bufA;
    float hx[16];
#pragma unroll
    for (int q = 0; q < 4; q++) {
        float4 v = in4[idx * 4 + q];
        hx[q * 4 + 0] = v.x; hx[q * 4 + 1] = v.y;
        hx[q * 4 + 2] = v.z; hx[q * 4 + 3] = v.w;
    }
    float acc[40];
#pragma unroll
    for (int c = 0; c < 40; c++) acc[c] = bs[c];
#pragma unroll
    for (int f = 0; f < 16; f++) {
        float xv = hx[f];
#pragma unroll
        for (int c = 0; c < 40; c++) acc[c] += xv * Ws[f * 40 + c];
    }
    float m = acc[0];
#pragma unroll
    for (int c = 1; c < 40; c++) m = fmaxf(m, acc[c]);
    float s = 0.f;
#pragma unroll
    for (int c = 0; c < 40; c++) s += __expf(acc[c] - m);
    float lse = m + __logf(s);
#pragma unroll
    for (int c = 0; c < 40; c++) out[idx * 40 + c] = acc[c] - lse;
}

// ---------------- launch ---------------------------------------------------
extern "C" void kernel_launch(void* const* d_in, const int* in_sizes, int n_in,
                              void* d_out, int out_size) {
    const float* x  = (const float*)d_in[0];
    const int*   ei = (const int*)d_in[1];     // int32! (JAX x64 disabled)
    const float* ew = (const float*)d_in[2];
    const float* Wf = (const float*)d_in[3];
    const float* bf = (const float*)d_in[4];
    const float* W1 = (const float*)d_in[5];
    const float* b1 = (const float*)d_in[6];
    const float* W2 = (const float*)d_in[7];
    const float* b2 = (const float*)d_in[8];
    const float* Wo = (const float*)d_in[9];
    const float* bo = (const float*)d_in[10];
    float* out = (float*)d_out;

    // resolve device-global buffer addresses for ping-pong
    float* bufA; float* bufB;
    cudaGetSymbolAddress((void**)&bufA, g_bufA);
    cudaGetSymbolAddress((void**)&bufB, g_bufB);

    int nb_n = (NN + 255) / 256;          // 391
    int nb_e = (EE + 255) / 256;          // 12500

    k_init   <<<nb_n, 256>>>();
    k_degcnt <<<nb_e, 256>>>(ei, ew);
    k_scan1  <<<SCAN_BLOCKS, 256>>>();
    k_scan2  <<<1, 128>>>();
    k_scan3  <<<SCAN_BLOCKS, 256>>>();
    k_scatter<<<nb_e, 256>>>(ei, ew);

    k_gemm1  <<<(NN + 255) / 256, 128>>>(x, Wf, bf);

    k_agg    <<<(NN * 16) / 256, 256>>>(bufA, bufB, W1, b1);
    k_agg    <<<(NN * 16) / 256, 256>>>(bufB, bufA, W2, b2);

    k_out    <<<nb_n, 256>>>(Wo, bo, out);
}